// round 8
// baseline (speedup 1.0000x reference)
#include <cuda_runtime.h>
#include <math.h>

#define NS 51
#define NITER 50
#define NT 64
#define PSTRIDE 53   // banks: (53t+m) mod 32 = (21t+m) mod 32, gcd(21,32)=1 -> conflict-free

// ---------------- constexpr double math (compile-time SSS table) ----------------
constexpr __host__ __device__ double cexp_(double x) {
    const double LN2     = 0.6931471805599453094172321;
    const double INV_LN2 = 1.4426950408889634073599247;
    const double t = x * INV_LN2;
    const long   k = (long)(t >= 0.0 ? t + 0.5 : t - 0.5);
    const double r = x - (double)k * LN2;          // |r| <= ~0.347
    double s = 7.647163731819816e-13;              // 1/15!
    s = s * r + 1.1470745597729725e-11;            // 1/14!
    s = s * r + 1.6059043836821613e-10;            // 1/13!
    s = s * r + 2.08767569878681e-9;               // 1/12!
    s = s * r + 2.505210838544172e-8;              // 1/11!
    s = s * r + 2.755731922398589e-7;              // 1/10!
    s = s * r + 2.755731922398589e-6;              // 1/9!
    s = s * r + 2.48015873015873e-5;               // 1/8!
    s = s * r + 1.984126984126984e-4;              // 1/7!
    s = s * r + 1.388888888888889e-3;              // 1/6!
    s = s * r + 8.333333333333333e-3;              // 1/5!
    s = s * r + 4.1666666666666664e-2;             // 1/4!
    s = s * r + 1.6666666666666666e-1;             // 1/3!
    s = s * r + 0.5;                               // 1/2!
    s = s * r + 1.0;                               // 1/1!
    s = s * r + 1.0;                               // 1/0!
    double pw = 1.0;
    const double base = (k >= 0) ? 2.0 : 0.5;
    long kk = (k >= 0) ? k : -k;
    for (long i = 0; i < kk; i++) pw *= base;
    return s * pw;
}
constexpr __host__ __device__ double csqrt_(double x) {
    double g = (x > 1.0) ? x : 1.0;
    for (int i = 0; i < 64; i++) g = 0.5 * (g + x / g);
    return g;
}

struct STab { float v[NS][NS]; };

constexpr __host__ __device__ STab make_stab() {
    STab tb{};
    const double RT      = (8.3144598 / 4184.0) * 623.15;
    const double fpol    = (3.667 - 1.0) / (3.667 + 0.5);
    const double aeff15  = 7.5 * csqrt_(7.5);
    const double alpha_p = fpol * (0.3 * aeff15 / 0.0002395);
    for (int m = 0; m < NS; m++) {
        for (int n = 0; n < NS; n++) {
            const double si = -0.025 + 0.001 * (double)m;
            const double sj = -0.025 + 0.001 * (double)n;
            const double smax = (si > sj) ? si : sj;
            const double smin = (si > sj) ? sj : si;
            double acc = smax - 0.0084; if (acc < 0.0) acc = 0.0;
            double don = smin + 0.0084; if (don > 0.0) don = 0.0;
            const double ss = si + sj;
            const double dw = 0.5 * alpha_p * ss * ss + 85580.0 * acc * don;
            const float dwf = (float)dw;
            tb.v[m][n] = (float)cexp_(-(double)dwf / RT);
        }
    }
    return tb;
}

// ---------------- kernel: one thread per (batch row, solve) ----------------
// tid even -> mix solve, tid odd -> pure solve. Pair communicates via shfl.
__global__ __launch_bounds__(NT, 7) void cosmo_imm_kernel(
    const float* __restrict__ my_g,    // [B,51]
    const float* __restrict__ vcomp,   // [B]
    const float* __restrict__ vtsig,   // [B,51,2]
    const float* __restrict__ vvt,     // [B]
    float* __restrict__ out,           // [B]
    int B)
{
    // Declared ONCE at function scope (like the passing R5 kernel). Declaring
    // this inside the iteration loop made NVVM materialize the 10.4KB table
    // into per-thread local memory (the R6/R7 4GB rule violation).
    constexpr STab STAB = make_stab();

    __shared__ float Psh[NT * PSTRIDE];   // 13568 B/block; 7 blocks -> 93 KB/SM

    const int t = threadIdx.x;
    const int tid = blockIdx.x * NT + t;
    int row = tid >> 1;
    const bool isPure = (tid & 1);
    if (row >= B) row = B - 1;         // clamp; keep warp convergent for shfl

    const float X0 = 0.235f, X1 = 1.0f - 0.235f;
    float* __restrict__ Pme = Psh + t * PSTRIDE;

    float H[NS], T[NS];

    float A0 = 0.f, A1 = 0.f;
    #pragma unroll
    for (int n = 0; n < NS; n++) { float m = my_g[row * NS + n]; T[n] = m; A0 += m; }
    #pragma unroll
    for (int n = 0; n < NS; n++) { float v = vtsig[(row * NS + n) * 2 + 1]; H[n] = v; A1 += v; }

    if (isPure) {
        const float inv = __fdividef(1.f, A0);
        #pragma unroll
        for (int n = 0; n < NS; n++) { float p = T[n] * inv; Pme[n] = p; H[n] = p; }
    } else {
        const float inv = __fdividef(1.f, X0 * A0 + X1 * A1);
        #pragma unroll
        for (int n = 0; n < NS; n++) { float p = fmaf(X0, T[n], X1 * H[n]) * inv; Pme[n] = p; H[n] = p; }
    }
    // Each thread touches only its own Pme slice -> no __syncthreads needed.

    // 50 iterations as 25 ping-pong pairs (no copy-back); SSS as FFMA immediates.
    #pragma unroll 1
    for (int it = 0; it < NITER / 2; it++) {
        #pragma unroll
        for (int m = 0; m < NS; m++) {
            float a0 = 0.f, a1 = 0.f, a2 = 0.f, a3 = 0.f;   // ILP=4 vs lat=4
            #pragma unroll
            for (int n = 0; n < NS - 3; n += 4) {
                a0 = fmaf(STAB.v[m][n+0], H[n+0], a0);
                a1 = fmaf(STAB.v[m][n+1], H[n+1], a1);
                a2 = fmaf(STAB.v[m][n+2], H[n+2], a2);
                a3 = fmaf(STAB.v[m][n+3], H[n+3], a3);
            }
            a0 = fmaf(STAB.v[m][48], H[48], a0);
            a1 = fmaf(STAB.v[m][49], H[49], a1);
            a2 = fmaf(STAB.v[m][50], H[50], a2);
            const float acc = (a0 + a1) + (a2 + a3);
            T[m] = 0.5f * fmaf(Pme[m], __fdividef(1.f, acc), H[m]);
        }
        #pragma unroll
        for (int m = 0; m < NS; m++) {
            float a0 = 0.f, a1 = 0.f, a2 = 0.f, a3 = 0.f;
            #pragma unroll
            for (int n = 0; n < NS - 3; n += 4) {
                a0 = fmaf(STAB.v[m][n+0], T[n+0], a0);
                a1 = fmaf(STAB.v[m][n+1], T[n+1], a1);
                a2 = fmaf(STAB.v[m][n+2], T[n+2], a2);
                a3 = fmaf(STAB.v[m][n+3], T[n+3], a3);
            }
            a0 = fmaf(STAB.v[m][48], T[48], a0);
            a1 = fmaf(STAB.v[m][49], T[49], a1);
            a2 = fmaf(STAB.v[m][50], T[50], a2);
            const float acc = (a0 + a1) + (a2 + a3);
            H[m] = 0.5f * fmaf(Pme[m], __fdividef(1.f, acc), T[m]);
        }
    }

    // Residual: pure lane accumulates sum_n P_pure[n]*(lnG_mix[n]-lnG_pure[n]).
    float resid = 0.f;
    #pragma unroll
    for (int n = 0; n < NS; n++) {
        const float p  = Pme[n];
        const float g  = logf(__fdividef(H[n], p));           // lnGamma this lane
        const float gp = __shfl_xor_sync(0xffffffffu, g, 1);  // partner's lnGamma
        resid = fmaf(p, gp - g, resid);
    }

    if (isPure && (tid >> 1) < B) {
        const float AEFF = 7.5f, Q0c = 79.53f, R0c = 66.69f;
        const float lng_resid = A0 * (1.0f / AEFF) * resid;
        const float q0 = A0 / Q0c, q1 = A1 / Q0c;
        const float r0 = vcomp[row] / R0c, r1 = vvt[row] / R0c;
        const float xq = X0 * q0 + X1 * q1;
        const float xr = X0 * r0 + X1 * r1;
        const float theta = X0 * q0 / xq;
        const float phi   = X0 * r0 / xr;
        const float l0 = 5.0f * (r0 - q0) - (r0 - 1.0f);
        const float l1 = 5.0f * (r1 - q1) - (r1 - 1.0f);
        const float xl = X0 * l0 + X1 * l1;
        const float lng_comb = logf(phi / X0) + 5.0f * q0 * logf(theta / phi)
                               + l0 - phi / X0 * xl;
        out[row] = lng_resid + lng_comb;
    }
}

extern "C" void kernel_launch(void* const* d_in, const int* in_sizes, int n_in,
                              void* d_out, int out_size)
{
    const int B = out_size;  // output is [B,1] float32
    const float* my = nullptr;
    const float* vt = nullptr;
    const float* vc = nullptr;
    const float* vv = nullptr;
    for (int i = 0; i < n_in; i++) {
        const long sz = in_sizes[i];
        if (sz == (long)B * NS)          my = (const float*)d_in[i];
        else if (sz == (long)B * NS * 2) vt = (const float*)d_in[i];
        else if (sz == (long)B) {
            if (!vc) vc = (const float*)d_in[i];
            else     vv = (const float*)d_in[i];
        }
    }
    const long threads = 2L * B;
    const int blocks = (int)((threads + NT - 1) / NT);   // 1024 for B=32768
    cosmo_imm_kernel<<<blocks, NT>>>(my, vc, vt, vv, (float*)d_out, B);
}

// round 9
// speedup vs baseline: 1.2107x; 1.2107x over previous
#include <cuda_runtime.h>
#include <math.h>

#define NS 51
#define NITER 50
#define NT 64
#define PSTRIDE 53   // banks: (53t+m) mod 32 = (21t+m) mod 32, gcd(21,32)=1 -> conflict-free

// ---------------- constexpr double math (compile-time SSS table) ----------------
constexpr __host__ __device__ double cexp_(double x) {
    const double LN2     = 0.6931471805599453094172321;
    const double INV_LN2 = 1.4426950408889634073599247;
    const double t = x * INV_LN2;
    const long   k = (long)(t >= 0.0 ? t + 0.5 : t - 0.5);
    const double r = x - (double)k * LN2;          // |r| <= ~0.347
    double s = 7.647163731819816e-13;              // 1/15!
    s = s * r + 1.1470745597729725e-11;            // 1/14!
    s = s * r + 1.6059043836821613e-10;            // 1/13!
    s = s * r + 2.08767569878681e-9;               // 1/12!
    s = s * r + 2.505210838544172e-8;              // 1/11!
    s = s * r + 2.755731922398589e-7;              // 1/10!
    s = s * r + 2.755731922398589e-6;              // 1/9!
    s = s * r + 2.48015873015873e-5;               // 1/8!
    s = s * r + 1.984126984126984e-4;              // 1/7!
    s = s * r + 1.388888888888889e-3;              // 1/6!
    s = s * r + 8.333333333333333e-3;              // 1/5!
    s = s * r + 4.1666666666666664e-2;             // 1/4!
    s = s * r + 1.6666666666666666e-1;             // 1/3!
    s = s * r + 0.5;                               // 1/2!
    s = s * r + 1.0;                               // 1/1!
    s = s * r + 1.0;                               // 1/0!
    double pw = 1.0;
    const double base = (k >= 0) ? 2.0 : 0.5;
    long kk = (k >= 0) ? k : -k;
    for (long i = 0; i < kk; i++) pw *= base;
    return s * pw;
}
constexpr __host__ __device__ double csqrt_(double x) {
    double g = (x > 1.0) ? x : 1.0;
    for (int i = 0; i < 64; i++) g = 0.5 * (g + x / g);
    return g;
}

struct STab { float v[NS][NS]; };

constexpr __host__ __device__ STab make_stab() {
    STab tb{};
    const double RT      = (8.3144598 / 4184.0) * 623.15;
    const double fpol    = (3.667 - 1.0) / (3.667 + 0.5);
    const double aeff15  = 7.5 * csqrt_(7.5);
    const double alpha_p = fpol * (0.3 * aeff15 / 0.0002395);
    for (int m = 0; m < NS; m++) {
        for (int n = 0; n < NS; n++) {
            const double si = -0.025 + 0.001 * (double)m;
            const double sj = -0.025 + 0.001 * (double)n;
            const double smax = (si > sj) ? si : sj;
            const double smin = (si > sj) ? sj : si;
            double acc = smax - 0.0084; if (acc < 0.0) acc = 0.0;
            double don = smin + 0.0084; if (don > 0.0) don = 0.0;
            const double ss = si + sj;
            const double dw = 0.5 * alpha_p * ss * ss + 85580.0 * acc * don;
            const float dwf = (float)dw;
            tb.v[m][n] = (float)cexp_(-(double)dwf / RT);
        }
    }
    return tb;
}

// ---------------- kernel: one thread per (batch row, solve) ----------------
// tid even -> mix solve, tid odd -> pure solve. Pair communicates via shfl.
__global__ __launch_bounds__(NT, 7) void cosmo_imm_kernel(
    const float* __restrict__ my_g,    // [B,51]
    const float* __restrict__ vcomp,   // [B]
    const float* __restrict__ vtsig,   // [B,51,2]
    const float* __restrict__ vvt,     // [B]
    float* __restrict__ out,           // [B]
    int B)
{
    // ONE function-scope declaration (R5-proven). Inside a loop body NVVM
    // materializes the 10.4KB table to local memory (R6/R7 4GB violation).
    constexpr STab STAB = make_stab();

    __shared__ float Psh[NT * PSTRIDE];   // 13568 B/block

    const int t = threadIdx.x;
    const int tid = blockIdx.x * NT + t;
    int row = tid >> 1;
    const bool isPure = (tid & 1);
    if (row >= B) row = B - 1;         // clamp; keep warp convergent for shfl

    const float X0 = 0.235f, X1 = 1.0f - 0.235f;
    float* __restrict__ Pme = Psh + t * PSTRIDE;

    float H[NS], T[NS];

    float A0 = 0.f, A1 = 0.f;
    #pragma unroll
    for (int n = 0; n < NS; n++) { float m = my_g[row * NS + n]; T[n] = m; A0 += m; }
    #pragma unroll
    for (int n = 0; n < NS; n++) { float v = vtsig[(row * NS + n) * 2 + 1]; H[n] = v; A1 += v; }

    if (isPure) {
        const float inv = __fdividef(1.f, A0);
        #pragma unroll
        for (int n = 0; n < NS; n++) { float p = T[n] * inv; Pme[n] = p; H[n] = p; }
    } else {
        const float inv = __fdividef(1.f, X0 * A0 + X1 * A1);
        #pragma unroll
        for (int n = 0; n < NS; n++) { float p = fmaf(X0, T[n], X1 * H[n]) * inv; Pme[n] = p; H[n] = p; }
    }
    // Each thread touches only its own Pme slice -> no __syncthreads needed.

    // Exact 50-step damped Jacobi. ONE matvec body (42KB SASS) + copy-back:
    // halves I$ footprint vs the two-body ping-pong. SSS as FFMA immediates.
    #pragma unroll 1
    for (int it = 0; it < NITER; it++) {
        #pragma unroll
        for (int m = 0; m < NS; m++) {
            float a0 = 0.f, a1 = 0.f, a2 = 0.f, a3 = 0.f;   // ILP=4 vs lat=4
            #pragma unroll
            for (int n = 0; n < NS - 3; n += 4) {
                a0 = fmaf(STAB.v[m][n+0], H[n+0], a0);
                a1 = fmaf(STAB.v[m][n+1], H[n+1], a1);
                a2 = fmaf(STAB.v[m][n+2], H[n+2], a2);
                a3 = fmaf(STAB.v[m][n+3], H[n+3], a3);
            }
            a0 = fmaf(STAB.v[m][48], H[48], a0);
            a1 = fmaf(STAB.v[m][49], H[49], a1);
            a2 = fmaf(STAB.v[m][50], H[50], a2);
            const float acc = (a0 + a1) + (a2 + a3);
            T[m] = 0.5f * fmaf(Pme[m], __fdividef(1.f, acc), H[m]);
        }
        #pragma unroll
        for (int n = 0; n < NS; n++) H[n] = T[n];
    }

    // Residual: pure lane accumulates sum_n P_pure[n]*(lnG_mix[n]-lnG_pure[n]).
    float resid = 0.f;
    #pragma unroll
    for (int n = 0; n < NS; n++) {
        const float p  = Pme[n];
        const float g  = logf(__fdividef(H[n], p));           // lnGamma this lane
        const float gp = __shfl_xor_sync(0xffffffffu, g, 1);  // partner's lnGamma
        resid = fmaf(p, gp - g, resid);
    }

    if (isPure && (tid >> 1) < B) {
        const float AEFF = 7.5f, Q0c = 79.53f, R0c = 66.69f;
        const float lng_resid = A0 * (1.0f / AEFF) * resid;
        const float q0 = A0 / Q0c, q1 = A1 / Q0c;
        const float r0 = vcomp[row] / R0c, r1 = vvt[row] / R0c;
        const float xq = X0 * q0 + X1 * q1;
        const float xr = X0 * r0 + X1 * r1;
        const float theta = X0 * q0 / xq;
        const float phi   = X0 * r0 / xr;
        const float l0 = 5.0f * (r0 - q0) - (r0 - 1.0f);
        const float l1 = 5.0f * (r1 - q1) - (r1 - 1.0f);
        const float xl = X0 * l0 + X1 * l1;
        const float lng_comb = logf(phi / X0) + 5.0f * q0 * logf(theta / phi)
                               + l0 - phi / X0 * xl;
        out[row] = lng_resid + lng_comb;
    }
}

extern "C" void kernel_launch(void* const* d_in, const int* in_sizes, int n_in,
                              void* d_out, int out_size)
{
    // Raise the L1/shared carveout so 7 blocks x 13.6KB of static smem fit:
    // default carveout (~48KB) capped residency at 3 blocks/SM (ncu occ=20.2%).
    // Idempotent host-side attribute set; not a stream op, capture-safe.
    cudaFuncSetAttribute(cosmo_imm_kernel,
                         cudaFuncAttributePreferredSharedMemoryCarveout, 100);

    const int B = out_size;  // output is [B,1] float32
    const float* my = nullptr;
    const float* vt = nullptr;
    const float* vc = nullptr;
    const float* vv = nullptr;
    for (int i = 0; i < n_in; i++) {
        const long sz = in_sizes[i];
        if (sz == (long)B * NS)          my = (const float*)d_in[i];
        else if (sz == (long)B * NS * 2) vt = (const float*)d_in[i];
        else if (sz == (long)B) {
            if (!vc) vc = (const float*)d_in[i];
            else     vv = (const float*)d_in[i];
        }
    }
    const long threads = 2L * B;
    const int blocks = (int)((threads + NT - 1) / NT);   // 1024 for B=32768
    cosmo_imm_kernel<<<blocks, NT>>>(my, vc, vt, vv, (float*)d_out, B);
}

// round 11
// speedup vs baseline: 1.2688x; 1.0480x over previous
#include <cuda_runtime.h>
#include <math.h>

#define NS 51
#define NITER 50
#define NT 64
#define PSTRIDE 53   // banks: (53t+m) mod 32 = (21t+m) mod 32, gcd(21,32)=1 -> conflict-free

// ---------------- constexpr double math (compile-time SSS table) ----------------
constexpr __host__ __device__ double cexp_(double x) {
    const double LN2     = 0.6931471805599453094172321;
    const double INV_LN2 = 1.4426950408889634073599247;
    const double t = x * INV_LN2;
    const long   k = (long)(t >= 0.0 ? t + 0.5 : t - 0.5);
    const double r = x - (double)k * LN2;          // |r| <= ~0.347
    double s = 7.647163731819816e-13;              // 1/15!
    s = s * r + 1.1470745597729725e-11;            // 1/14!
    s = s * r + 1.6059043836821613e-10;            // 1/13!
    s = s * r + 2.08767569878681e-9;               // 1/12!
    s = s * r + 2.505210838544172e-8;              // 1/11!
    s = s * r + 2.755731922398589e-7;              // 1/10!
    s = s * r + 2.755731922398589e-6;              // 1/9!
    s = s * r + 2.48015873015873e-5;               // 1/8!
    s = s * r + 1.984126984126984e-4;              // 1/7!
    s = s * r + 1.388888888888889e-3;              // 1/6!
    s = s * r + 8.333333333333333e-3;              // 1/5!
    s = s * r + 4.1666666666666664e-2;             // 1/4!
    s = s * r + 1.6666666666666666e-1;             // 1/3!
    s = s * r + 0.5;                               // 1/2!
    s = s * r + 1.0;                               // 1/1!
    s = s * r + 1.0;                               // 1/0!
    double pw = 1.0;
    const double base = (k >= 0) ? 2.0 : 0.5;
    long kk = (k >= 0) ? k : -k;
    for (long i = 0; i < kk; i++) pw *= base;
    return s * pw;
}
constexpr __host__ __device__ double csqrt_(double x) {
    double g = (x > 1.0) ? x : 1.0;
    for (int i = 0; i < 64; i++) g = 0.5 * (g + x / g);
    return g;
}

struct STab { float v[NS][NS]; };

constexpr __host__ __device__ STab make_stab() {
    STab tb{};
    const double RT      = (8.3144598 / 4184.0) * 623.15;
    const double fpol    = (3.667 - 1.0) / (3.667 + 0.5);
    const double aeff15  = 7.5 * csqrt_(7.5);
    const double alpha_p = fpol * (0.3 * aeff15 / 0.0002395);
    for (int m = 0; m < NS; m++) {
        for (int n = 0; n < NS; n++) {
            const double si = -0.025 + 0.001 * (double)m;
            const double sj = -0.025 + 0.001 * (double)n;
            const double smax = (si > sj) ? si : sj;
            const double smin = (si > sj) ? sj : si;
            double acc = smax - 0.0084; if (acc < 0.0) acc = 0.0;
            double don = smin + 0.0084; if (don > 0.0) don = 0.0;
            const double ss = si + sj;
            const double dw = 0.5 * alpha_p * ss * ss + 85580.0 * acc * don;
            const float dwf = (float)dw;
            tb.v[m][n] = (float)cexp_(-(double)dwf / RT);
        }
    }
    return tb;
}

// ---------------- kernel: one thread per (batch row, solve) ----------------
// tid even -> mix solve, tid odd -> pure solve. Pair communicates via shfl.
// EXACT 50-step damped Jacobi (R10 proved the output is trajectory-defined:
// in-place/GS ordering gave rel_err 9e-2). Row-PAIR interleaving: two rows'
// accumulator chains and MUFU tails overlap, raising issue efficiency.
__global__ __launch_bounds__(NT, 8) void cosmo_imm_kernel(
    const float* __restrict__ my_g,    // [B,51]
    const float* __restrict__ vcomp,   // [B]
    const float* __restrict__ vtsig,   // [B,51,2]
    const float* __restrict__ vvt,     // [B]
    float* __restrict__ out,           // [B]
    int B)
{
    // ONE function-scope declaration (R5-proven). Inside a loop body NVVM
    // materializes the 10.4KB table to local memory (R6/R7 4GB violation).
    constexpr STab STAB = make_stab();

    __shared__ float Psh[NT * PSTRIDE];   // 13568 B/block

    const int t = threadIdx.x;
    const int tid = blockIdx.x * NT + t;
    int row = tid >> 1;
    const bool isPure = (tid & 1);
    if (row >= B) row = B - 1;         // clamp; keep warp convergent for shfl

    const float X0 = 0.235f, X1 = 1.0f - 0.235f;
    float* __restrict__ Pme = Psh + t * PSTRIDE;

    float H[NS], T[NS];

    float A0 = 0.f, A1 = 0.f;
    #pragma unroll
    for (int n = 0; n < NS; n++) { float m = my_g[row * NS + n]; T[n] = m; A0 += m; }
    #pragma unroll
    for (int n = 0; n < NS; n++) { float v = vtsig[(row * NS + n) * 2 + 1]; H[n] = v; A1 += v; }

    if (isPure) {
        const float inv = __fdividef(1.f, A0);
        #pragma unroll
        for (int n = 0; n < NS; n++) { float p = T[n] * inv; Pme[n] = p; H[n] = p; }
    } else {
        const float inv = __fdividef(1.f, X0 * A0 + X1 * A1);
        #pragma unroll
        for (int n = 0; n < NS; n++) { float p = fmaf(X0, T[n], X1 * H[n]) * inv; Pme[n] = p; H[n] = p; }
    }
    // Each thread touches only its own Pme slice -> no __syncthreads needed.

    // Exact Jacobi-50, double buffered (H -> T, then copy back).
    // Rows processed in PAIRS: 8 accumulators, two overlapping tails.
    #pragma unroll 1
    for (int it = 0; it < NITER; it++) {
        #pragma unroll
        for (int m = 0; m < NS - 1; m += 2) {
            float a0 = 0.f, a1 = 0.f, a2 = 0.f, a3 = 0.f;
            float b0 = 0.f, b1 = 0.f, b2 = 0.f, b3 = 0.f;
            #pragma unroll
            for (int n = 0; n < NS - 3; n += 4) {
                a0 = fmaf(STAB.v[m  ][n+0], H[n+0], a0);
                b0 = fmaf(STAB.v[m+1][n+0], H[n+0], b0);
                a1 = fmaf(STAB.v[m  ][n+1], H[n+1], a1);
                b1 = fmaf(STAB.v[m+1][n+1], H[n+1], b1);
                a2 = fmaf(STAB.v[m  ][n+2], H[n+2], a2);
                b2 = fmaf(STAB.v[m+1][n+2], H[n+2], b2);
                a3 = fmaf(STAB.v[m  ][n+3], H[n+3], a3);
                b3 = fmaf(STAB.v[m+1][n+3], H[n+3], b3);
            }
            a0 = fmaf(STAB.v[m  ][48], H[48], a0);
            b0 = fmaf(STAB.v[m+1][48], H[48], b0);
            a1 = fmaf(STAB.v[m  ][49], H[49], a1);
            b1 = fmaf(STAB.v[m+1][49], H[49], b1);
            a2 = fmaf(STAB.v[m  ][50], H[50], a2);
            b2 = fmaf(STAB.v[m+1][50], H[50], b2);
            const float accA = (a0 + a1) + (a2 + a3);
            const float accB = (b0 + b1) + (b2 + b3);
            T[m]   = 0.5f * fmaf(Pme[m],   __fdividef(1.f, accA), H[m]);
            T[m+1] = 0.5f * fmaf(Pme[m+1], __fdividef(1.f, accB), H[m+1]);
        }
        {   // last row (m = 50)
            const int m = NS - 1;
            float a0 = 0.f, a1 = 0.f, a2 = 0.f, a3 = 0.f;
            #pragma unroll
            for (int n = 0; n < NS - 3; n += 4) {
                a0 = fmaf(STAB.v[m][n+0], H[n+0], a0);
                a1 = fmaf(STAB.v[m][n+1], H[n+1], a1);
                a2 = fmaf(STAB.v[m][n+2], H[n+2], a2);
                a3 = fmaf(STAB.v[m][n+3], H[n+3], a3);
            }
            a0 = fmaf(STAB.v[m][48], H[48], a0);
            a1 = fmaf(STAB.v[m][49], H[49], a1);
            a2 = fmaf(STAB.v[m][50], H[50], a2);
            const float acc = (a0 + a1) + (a2 + a3);
            T[m] = 0.5f * fmaf(Pme[m], __fdividef(1.f, acc), H[m]);
        }
        #pragma unroll
        for (int n = 0; n < NS; n++) H[n] = T[n];
    }

    // Residual: pure lane accumulates sum_n P_pure[n]*(lnG_mix[n]-lnG_pure[n]).
    float resid = 0.f;
    #pragma unroll
    for (int n = 0; n < NS; n++) {
        const float p  = Pme[n];
        const float g  = logf(__fdividef(H[n], p));           // lnGamma this lane
        const float gp = __shfl_xor_sync(0xffffffffu, g, 1);  // partner's lnGamma
        resid = fmaf(p, gp - g, resid);
    }

    if (isPure && (tid >> 1) < B) {
        const float AEFF = 7.5f, Q0c = 79.53f, R0c = 66.69f;
        const float lng_resid = A0 * (1.0f / AEFF) * resid;
        const float q0 = A0 / Q0c, q1 = A1 / Q0c;
        const float r0 = vcomp[row] / R0c, r1 = vvt[row] / R0c;
        const float xq = X0 * q0 + X1 * q1;
        const float xr = X0 * r0 + X1 * r1;
        const float theta = X0 * q0 / xq;
        const float phi   = X0 * r0 / xr;
        const float l0 = 5.0f * (r0 - q0) - (r0 - 1.0f);
        const float l1 = 5.0f * (r1 - q1) - (r1 - 1.0f);
        const float xl = X0 * l0 + X1 * l1;
        const float lng_comb = logf(phi / X0) + 5.0f * q0 * logf(theta / phi)
                               + l0 - phi / X0 * xl;
        out[row] = lng_resid + lng_comb;
    }
}

extern "C" void kernel_launch(void* const* d_in, const int* in_sizes, int n_in,
                              void* d_out, int out_size)
{
    // Max L1/shared carveout so 8 blocks x 13.6KB static smem can be resident.
    cudaFuncSetAttribute(cosmo_imm_kernel,
                         cudaFuncAttributePreferredSharedMemoryCarveout, 100);

    const int B = out_size;  // output is [B,1] float32
    const float* my = nullptr;
    const float* vt = nullptr;
    const float* vc = nullptr;
    const float* vv = nullptr;
    for (int i = 0; i < n_in; i++) {
        const long sz = in_sizes[i];
        if (sz == (long)B * NS)          my = (const float*)d_in[i];
        else if (sz == (long)B * NS * 2) vt = (const float*)d_in[i];
        else if (sz == (long)B) {
            if (!vc) vc = (const float*)d_in[i];
            else     vv = (const float*)d_in[i];
        }
    }
    const long threads = 2L * B;
    const int blocks = (int)((threads + NT - 1) / NT);   // 1024 for B=32768
    cosmo_imm_kernel<<<blocks, NT>>>(my, vc, vt, vv, (float*)d_out, B);
}